// round 1
// baseline (speedup 1.0000x reference)
#include <cuda_runtime.h>

// Problem shape (fixed by reference)
#define B_ 16
#define T_ 4096
#define D_ 512
#define C_ 32          // chunks along T
#define L_ 128         // T_/C_ steps per chunk

// Scratch (static __device__ — no allocation allowed in kernel_launch).
// end state of each chunk computed with zero-init, and the carry entering each chunk.
__device__ float2 g_end  [B_ * C_ * D_];   // 2 MB
__device__ float2 g_carry[B_ * C_ * D_];   // 2 MB

// ---------------------------------------------------------------------------
// Pass A: per-chunk local scan with zero initial state; store end state.
// grid = (C_, B_), block = D_ threads (one per d). Coalesced: at each t-step
// the 512 threads read 512 contiguous floats.
// ---------------------------------------------------------------------------
__global__ void __launch_bounds__(D_) chunk_end_kernel(
    const float* __restrict__ x,
    const float* __restrict__ Ar,
    const float* __restrict__ Ai)
{
    const int d = threadIdx.x;
    const int c = blockIdx.x;
    const int b = blockIdx.y;

    const float ar = Ar[d];
    const float ai = Ai[d];

    const float* xp = x + ((size_t)b * T_ + (size_t)c * L_) * D_ + d;

    float sr = 0.0f, si = 0.0f;
    #pragma unroll 8
    for (int i = 0; i < L_; ++i) {
        const float xv = xp[(size_t)i * D_];
        const float nr = fmaf(sr, ar, fmaf(-si, ai, xv));
        const float ni = fmaf(sr, ai, si * ar);
        sr = nr; si = ni;
    }
    g_end[((size_t)b * C_ + c) * D_ + d] = make_float2(sr, si);
}

// ---------------------------------------------------------------------------
// Pass B: sequential combine over the C_=32 chunks of each (b,d) series.
// One thread per series (8192 threads total). Combine rule:
//   state_end(c) = A^L * carry_in(c) + end(c) ;  carry_in(c+1) = state_end(c)
// A^L computed by 7 complex squarings (L = 2^7).
// Loads of g_end are coalesced across threads (adjacent d).
// ---------------------------------------------------------------------------
__global__ void carry_scan_kernel(
    const float* __restrict__ Ar,
    const float* __restrict__ Ai)
{
    const int idx = blockIdx.x * blockDim.x + threadIdx.x;  // = b*D_ + d
    const int d = idx & (D_ - 1);
    const int b = idx >> 9;   // / D_

    float pr = Ar[d], pi = Ai[d];
    #pragma unroll
    for (int k = 0; k < 7; ++k) {           // A^(2^7) = A^128 = A^L
        const float nr = pr * pr - pi * pi;
        const float ni = 2.0f * pr * pi;
        pr = nr; pi = ni;
    }

    float cr = 0.0f, ci = 0.0f;
    #pragma unroll
    for (int c = 0; c < C_; ++c) {
        const size_t off = ((size_t)b * C_ + c) * D_ + d;
        g_carry[off] = make_float2(cr, ci);
        const float2 e = g_end[off];
        const float nr = fmaf(pr, cr, fmaf(-pi, ci, e.x));
        const float ni = fmaf(pi, cr, fmaf(pr, ci, e.y));
        cr = nr; ci = ni;
    }
}

// ---------------------------------------------------------------------------
// Pass C: recompute each chunk's scan starting from its carry; emit outputs.
// float2 stores (Re, Im) — contiguous and coalesced along d.
// ---------------------------------------------------------------------------
__global__ void __launch_bounds__(D_) output_kernel(
    const float* __restrict__ x,
    const float* __restrict__ Ar,
    const float* __restrict__ Ai,
    float2* __restrict__ out)
{
    const int d = threadIdx.x;
    const int c = blockIdx.x;
    const int b = blockIdx.y;

    const float ar = Ar[d];
    const float ai = Ai[d];

    const float2 cv = g_carry[((size_t)b * C_ + c) * D_ + d];
    float sr = cv.x, si = cv.y;

    const float* xp = x   + ((size_t)b * T_ + (size_t)c * L_) * D_ + d;
    float2*      op = out + ((size_t)b * T_ + (size_t)c * L_) * D_ + d;

    #pragma unroll 8
    for (int i = 0; i < L_; ++i) {
        const float xv = xp[(size_t)i * D_];
        const float nr = fmaf(sr, ar, fmaf(-si, ai, xv));
        const float ni = fmaf(sr, ai, si * ar);
        sr = nr; si = ni;
        op[(size_t)i * D_] = make_float2(nr, ni);
    }
}

// ---------------------------------------------------------------------------
// kernel_launch: 3 dependent launches on the capture stream.
// Inputs (metadata order): x [B*T*D] f32, A_real [D] f32, A_imag [D] f32.
// Output: [B, T, D, 2] f32.
// ---------------------------------------------------------------------------
extern "C" void kernel_launch(void* const* d_in, const int* in_sizes, int n_in,
                              void* d_out, int out_size)
{
    const float* x  = (const float*)d_in[0];
    const float* Ar = (const float*)d_in[1];
    const float* Ai = (const float*)d_in[2];
    float2* out = (float2*)d_out;

    dim3 grid(C_, B_);
    chunk_end_kernel<<<grid, D_>>>(x, Ar, Ai);
    carry_scan_kernel<<<(B_ * D_) / 256, 256>>>(Ar, Ai);
    output_kernel<<<grid, D_>>>(x, Ar, Ai, out);
}